// round 14
// baseline (speedup 1.0000x reference)
#include <cuda_runtime.h>

// SpatialTransformer: out[b,c,y,x] = bilinear_sample_zeros(src[b,c], y+flow[b,0,y,x], x+flow[b,1,y,x])
// src [8,64,256,256] f32, flow [8,2,256,256] f32, out [8,64,256,256] f32.
//
// R13: R2 kernel (proven-optimal mapping: warp = 32 consecutive x, 4 scattered
// LDG.32 taps, weights/offsets in registers) with the channel work per block
// doubled to 16 via an OUTER loop that reuses the same weight/offset registers
// (unlike R12's explicit pipeline, adds no live values). __launch_bounds__(256,8)
// pins regs at 32 so occupancy stays at R2's ~90%. Halves flow-load + prologue
// cost per output; gather wavefronts untouched.

#define B_ 8
#define C_ 64
#define H_ 256
#define W_ 256
#define PLANE (H_ * W_)
#define CPB 16   // channels per block
#define CIN 8    // inner unrolled channels
#define GRP (CPB / CIN)  // outer loop trips = 2

__global__ __launch_bounds__(256, 8) void st_cpt16_kernel(
    const float* __restrict__ src,
    const float* __restrict__ flow,
    float* __restrict__ out)
{
    const int x  = threadIdx.x;        // 0..255
    const int y  = blockIdx.x;         // 0..255
    const int cg = blockIdx.y;         // 0..3   (group of 16 channels)
    const int b  = blockIdx.z;         // 0..7

    // ---- per-(b,y,x) prologue (identical math to R2) ----
    const int fbase = b * 2 * PLANE + y * W_ + x;
    const float py = (float)y + __ldg(flow + fbase);           // flow ch 0 = dy
    const float px = (float)x + __ldg(flow + fbase + PLANE);   // flow ch 1 = dx

    const float y0f = floorf(py);
    const float x0f = floorf(px);
    float wy1 = py - y0f;
    float wx1 = px - x0f;
    float wy0 = 1.0f - wy1;
    float wx0 = 1.0f - wx1;

    const int y0 = (int)y0f;
    const int x0 = (int)x0f;
    const int y1 = y0 + 1;
    const int x1 = x0 + 1;

    // zeros padding folded into 1D weights
    wy0 = ((unsigned)y0 < (unsigned)H_) ? wy0 : 0.0f;
    wy1 = ((unsigned)y1 < (unsigned)H_) ? wy1 : 0.0f;
    wx0 = ((unsigned)x0 < (unsigned)W_) ? wx0 : 0.0f;
    wx1 = ((unsigned)x1 < (unsigned)W_) ? wx1 : 0.0f;

    const float w00 = wy0 * wx0;
    const float w01 = wy0 * wx1;
    const float w10 = wy1 * wx0;
    const float w11 = wy1 * wx1;

    // clamped coords (invalid taps carry weight 0)
    const int yc0 = min(max(y0, 0), H_ - 1);
    const int yc1 = min(max(y1, 0), H_ - 1);
    const int xc0 = min(max(x0, 0), W_ - 1);
    const int xc1 = min(max(x1, 0), W_ - 1);

    const int o00 = yc0 * W_ + xc0;
    const int o01 = yc0 * W_ + xc1;
    const int o10 = yc1 * W_ + xc0;
    const int o11 = yc1 * W_ + xc1;

    // ---- channel loops: outer reuses all prologue registers ----
    const int c0 = cg * CPB;
    const float* s = src + (size_t)(b * C_ + c0) * PLANE;
    float*       o = out + (size_t)(b * C_ + c0) * PLANE + y * W_ + x;

    for (int g = 0; g < GRP; ++g) {
        #pragma unroll
        for (int c = 0; c < CIN; ++c) {
            const float v00 = __ldg(s + o00);
            const float v01 = __ldg(s + o01);
            const float v10 = __ldg(s + o10);
            const float v11 = __ldg(s + o11);
            o[c * PLANE] = w00 * v00 + w01 * v01 + w10 * v10 + w11 * v11;
            s += PLANE;
        }
        o += CIN * PLANE;
    }
}

extern "C" void kernel_launch(void* const* d_in, const int* in_sizes, int n_in,
                              void* d_out, int out_size)
{
    const float* src  = (const float*)d_in[0];
    const float* flow = (const float*)d_in[1];
    float* out = (float*)d_out;

    dim3 grid(H_, C_ / CPB, B_);   // (256, 4, 8) = 8192 blocks
    dim3 block(W_);                // 256 threads, one per x
    st_cpt16_kernel<<<grid, block>>>(src, flow, out);
}